// round 8
// baseline (speedup 1.0000x reference)
#include <cuda_runtime.h>
#include <cuda_bf16.h>
#include <math.h>

#define B_ 16
#define T_ 256
#define H_ 128
#define E_ 128
#define V_ 50000
#define G_ 512   /* 4*H */

// ---------------- scratch (no allocation allowed) ----------------
__device__ float g_xproj[(size_t)T_ * B_ * G_];   // 8 MB, reused by both layers
__device__ float g_y0[(size_t)T_ * B_ * H_];      // 2 MB, layout [T,B,H]
__device__ float g_y1[(size_t)B_ * T_ * H_];      // 2 MB, layout [B,T,H]

// ---------------- packed fp32x2 helpers (Blackwell FFMA2 path) ----------------
static __device__ __forceinline__ unsigned long long pk2(float x, float y) {
    unsigned long long r;
    asm("mov.b64 %0, {%1, %2};" : "=l"(r) : "f"(x), "f"(y));
    return r;
}
static __device__ __forceinline__ float2 upk2(unsigned long long v) {
    float2 r;
    asm("mov.b64 {%0, %1}, %2;" : "=f"(r.x), "=f"(r.y) : "l"(v));
    return r;
}
static __device__ __forceinline__ unsigned long long ffma2(
    unsigned long long a, unsigned long long b, unsigned long long c) {
    unsigned long long d;
    asm("fma.rn.f32x2 %0, %1, %2, %3;" : "=l"(d) : "l"(a), "l"(b), "l"(c));
    return d;
}

static __device__ __forceinline__ float sigf(float x) {
    return 1.0f / (1.0f + expf(-x));
}

// =====================================================================
// proj GEMM: out[r][g] = dot(A(r,:), Wih[g,:]) + bih[g] + bhh[g]
// rows r = t*B + b (4096 rows), N = 512, K = 128.
// If xidx != null, A row = emb[x[b][t]] (fused embedding gather).
// Tile 64x64, 256 threads, full-K in smem.
// =====================================================================
#define PROJ_SMEM (64 * 132 * 4 + 128 * 65 * 4)

__global__ __launch_bounds__(256) void proj_kernel(
    const float* __restrict__ Asrc, const int* __restrict__ xidx,
    const float* __restrict__ Wih, const float* __restrict__ bih,
    const float* __restrict__ bhh, float* __restrict__ out)
{
    extern __shared__ float sm[];
    float (*As)[132] = reinterpret_cast<float(*)[132]>(sm);          // 64 x 128 (+pad)
    float (*Ws)[65]  = reinterpret_cast<float(*)[65]>(sm + 64 * 132); // Ws[k][n]

    const int m0 = blockIdx.y * 64;
    const int n0 = blockIdx.x * 64;
    const int tid = threadIdx.x;

    // Load A tile (gathered for layer 0)
    for (int i = tid; i < 64 * 32; i += 256) {
        int r = i >> 5, c4 = (i & 31) * 4;
        const float* arow;
        if (xidx) {
            int gr = m0 + r;                 // gr = t*16 + b
            int b = gr & 15, t = gr >> 4;
            arow = Asrc + (size_t)xidx[b * T_ + t] * E_;
        } else {
            arow = Asrc + (size_t)(m0 + r) * H_;
        }
        float4 v = *reinterpret_cast<const float4*>(arow + c4);
        *reinterpret_cast<float4*>(&As[r][c4]) = v;
    }
    // Load W tile transposed: Ws[k][n] = Wih[n0+n][k]
    for (int i = tid; i < 64 * 32; i += 256) {
        int n = i >> 5, c4 = (i & 31) * 4;
        float4 v = *reinterpret_cast<const float4*>(Wih + (size_t)(n0 + n) * 128 + c4);
        Ws[c4 + 0][n] = v.x; Ws[c4 + 1][n] = v.y;
        Ws[c4 + 2][n] = v.z; Ws[c4 + 3][n] = v.w;
    }
    __syncthreads();

    const int tx = tid & 15, ty = tid >> 4;
    float acc[4][4] = {};
    #pragma unroll 8
    for (int k = 0; k < 128; k++) {
        float a[4], w[4];
        #pragma unroll
        for (int i = 0; i < 4; i++) a[i] = As[ty * 4 + i][k];
        #pragma unroll
        for (int j = 0; j < 4; j++) w[j] = Ws[k][tx * 4 + j];
        #pragma unroll
        for (int i = 0; i < 4; i++)
            #pragma unroll
            for (int j = 0; j < 4; j++)
                acc[i][j] = fmaf(a[i], w[j], acc[i][j]);
    }

    #pragma unroll
    for (int j = 0; j < 4; j++) {
        int n = n0 + tx * 4 + j;
        float bv = bih[n] + bhh[n];
        #pragma unroll
        for (int i = 0; i < 4; i++) {
            out[(size_t)(m0 + ty * 4 + i) * G_ + n] = acc[i][j] + bv;
        }
    }
}

// =====================================================================
// LSTM recurrence: one block per batch element (16 blocks), 512 threads
// (one gate each). h state in smem (broadcast reads), c in registers of
// threads 0..127. Gate dot products via packed fp32x2 FMA.
// layer==0: y layout [T,B,H]; layer==1: y layout [B,T,H].
// =====================================================================
__global__ __launch_bounds__(512, 1) void lstm_kernel(
    const float* __restrict__ xproj, const float* __restrict__ Whh,
    float* __restrict__ y, int layer,
    float* __restrict__ h_out, float* __restrict__ c_out)
{
    __shared__ float hs[H_];
    __shared__ float gs[G_];
    const int b = blockIdx.x;
    const int g = threadIdx.x;

    float c = 0.0f;
    if (g < H_) hs[g] = 0.0f;
    __syncthreads();

    const float4* w4 = reinterpret_cast<const float4*>(Whh + (size_t)g * H_);

    for (int t = 0; t < T_; t++) {
        unsigned long long acc = 0ull;  // packed {0.f, 0.f}
        const float4* h4 = reinterpret_cast<const float4*>(hs);
        #pragma unroll
        for (int k = 0; k < H_ / 4; k++) {
            float4 wv = w4[k];
            float4 hv = h4[k];
            acc = ffma2(pk2(wv.x, wv.y), pk2(hv.x, hv.y), acc);
            acc = ffma2(pk2(wv.z, wv.w), pk2(hv.z, hv.w), acc);
        }
        float2 p = upk2(acc);
        gs[g] = p.x + p.y + xproj[((size_t)t * B_ + b) * G_ + g];
        __syncthreads();

        if (g < H_) {
            float iv = sigf(gs[g]);
            float fv = sigf(gs[H_ + g]);
            float gv = tanhf(gs[2 * H_ + g]);
            float ov = sigf(gs[3 * H_ + g]);
            c = fv * c + iv * gv;
            float h = ov * tanhf(c);
            hs[g] = h;
            size_t row = (layer == 0) ? ((size_t)t * B_ + b) : ((size_t)b * T_ + t);
            y[row * H_ + g] = h;
        }
        __syncthreads();
    }

    if (g < H_) {
        h_out[b * H_ + g] = hs[g];
        c_out[b * H_ + g] = c;
    }
}

// =====================================================================
// FC GEMM: logits[r][v] = dot(y1[r,:], fc_w[v,:]) + fc_b[v]
// M=4096, N=50000, K=128. Tile 128x128, 256 threads, full K in smem.
// Packed fp32x2 over k-pairs: one FFMA2 = 2 fp32 FMAs (bit-exact fp32).
// B staged k2-major so per-k2 b-loads are 16 consecutive float2
// (conflict-free); thread columns are j*16+tx (coalesced stores).
// =====================================================================
#define FC_SMEM (128 * 132 * 4 + 64 * 128 * 8)

__global__ __launch_bounds__(256, 1) void fc_kernel(
    const float* __restrict__ A, const float* __restrict__ W,
    const float* __restrict__ bias, float* __restrict__ out)
{
    extern __shared__ float sm[];
    float (*As)[132] = reinterpret_cast<float(*)[132]>(sm);                 // 128 x 128 (+pad)
    unsigned long long* Bs = reinterpret_cast<unsigned long long*>(sm + 128 * 132); // [64 k2][128 n]

    const int n0 = blockIdx.x * 128;
    const int m0 = blockIdx.y * 128;
    const int tid = threadIdx.x;

    for (int i = tid; i < 128 * 32; i += 256) {
        int r = i >> 5, c4 = (i & 31) * 4;
        float4 v = *reinterpret_cast<const float4*>(A + (size_t)(m0 + r) * H_ + c4);
        *reinterpret_cast<float4*>(&As[r][c4]) = v;
    }
    for (int i = tid; i < 128 * 32; i += 256) {
        int n = i >> 5, c4 = i & 31;
        int vrow = n0 + n;
        float4 v = (vrow < V_)
            ? *reinterpret_cast<const float4*>(W + (size_t)vrow * H_ + c4 * 4)
            : make_float4(0.f, 0.f, 0.f, 0.f);
        Bs[(size_t)(2 * c4) * 128 + n]     = pk2(v.x, v.y);
        Bs[(size_t)(2 * c4 + 1) * 128 + n] = pk2(v.z, v.w);
    }
    __syncthreads();

    const int tx = tid & 15, ty = tid >> 4;
    unsigned long long acc[8][8];
    #pragma unroll
    for (int i = 0; i < 8; i++)
        #pragma unroll
        for (int j = 0; j < 8; j++) acc[i][j] = 0ull;

    #pragma unroll 8
    for (int k2 = 0; k2 < 64; k2++) {
        unsigned long long a[8], bb[8];
        #pragma unroll
        for (int i = 0; i < 8; i++) {
            float2 av = *reinterpret_cast<const float2*>(&As[ty * 8 + i][2 * k2]);
            a[i] = pk2(av.x, av.y);
        }
        #pragma unroll
        for (int j = 0; j < 8; j++) bb[j] = Bs[(size_t)k2 * 128 + j * 16 + tx];
        #pragma unroll
        for (int i = 0; i < 8; i++)
            #pragma unroll
            for (int j = 0; j < 8; j++)
                acc[i][j] = ffma2(a[i], bb[j], acc[i][j]);
    }

    #pragma unroll
    for (int j = 0; j < 8; j++) {
        int n = n0 + j * 16 + tx;
        if (n < V_) {
            float bv = bias[n];
            #pragma unroll
            for (int i = 0; i < 8; i++) {
                float2 p = upk2(acc[i][j]);
                out[(size_t)(m0 + ty * 8 + i) * V_ + n] = p.x + p.y + bv;
            }
        }
    }
}

// =====================================================================
// launch
// =====================================================================
extern "C" void kernel_launch(void* const* d_in, const int* in_sizes, int n_in,
                              void* d_out, int out_size)
{
    const int*   x    = (const int*)  d_in[0];
    const float* emb  = (const float*)d_in[1];
    const float* Wih0 = (const float*)d_in[2];
    const float* Whh0 = (const float*)d_in[3];
    const float* bih0 = (const float*)d_in[4];
    const float* bhh0 = (const float*)d_in[5];
    const float* Wih1 = (const float*)d_in[6];
    const float* Whh1 = (const float*)d_in[7];
    const float* bih1 = (const float*)d_in[8];
    const float* bhh1 = (const float*)d_in[9];
    const float* fcw  = (const float*)d_in[10];
    const float* fcb  = (const float*)d_in[11];
    float* out = (float*)d_out;

    float *xproj, *y0, *y1;
    cudaGetSymbolAddress((void**)&xproj, g_xproj);
    cudaGetSymbolAddress((void**)&y0, g_y0);
    cudaGetSymbolAddress((void**)&y1, g_y1);

    cudaFuncSetAttribute(proj_kernel, cudaFuncAttributeMaxDynamicSharedMemorySize, PROJ_SMEM);
    cudaFuncSetAttribute(fc_kernel,  cudaFuncAttributeMaxDynamicSharedMemorySize, FC_SMEM);

    // output layout: logits [B,T,V] || h [L,B,H] || c [L,B,H]
    const size_t NL = (size_t)B_ * T_ * V_;
    float* h_base = out + NL;
    float* c_base = out + NL + 2 * B_ * H_;

    // layer 0
    proj_kernel<<<dim3(8, 64), 256, PROJ_SMEM>>>(emb, x, Wih0, bih0, bhh0, xproj);
    lstm_kernel<<<16, 512>>>(xproj, Whh0, y0, 0, h_base, c_base);
    // layer 1
    proj_kernel<<<dim3(8, 64), 256, PROJ_SMEM>>>(y0, nullptr, Wih1, bih1, bhh1, xproj);
    lstm_kernel<<<16, 512>>>(xproj, Whh1, y1, 1, h_base + B_ * H_, c_base + B_ * H_);
    // output projection
    fc_kernel<<<dim3((V_ + 127) / 128, 32), 256, FC_SMEM>>>(y1, fcw, fcb, out);
}

// round 13
// speedup vs baseline: 4.5580x; 4.5580x over previous
#include <cuda_runtime.h>
#include <cuda_bf16.h>
#include <math.h>
#include <stdint.h>

#define B_ 16
#define T_ 256
#define H_ 128
#define E_ 128
#define V_ 50000
#define VP_ 50176  /* padded vocab rows for guard-free staging */
#define G_ 512     /* 4*H */

// ---------------- scratch (no allocation allowed) ----------------
__device__ float g_xproj[(size_t)T_ * B_ * G_];          // 8 MB
__device__ float g_y0[(size_t)T_ * B_ * H_];             // layer0 out [T,B,H] fp32
__device__ __nv_bfloat16 g_ah[(size_t)B_ * T_ * H_];     // layer1 out hi bf16 [B,T,H]
__device__ __nv_bfloat16 g_al[(size_t)B_ * T_ * H_];     // layer1 out lo bf16 [B,T,H]
__device__ __nv_bfloat16 g_wh[(size_t)VP_ * H_];         // fc_w hi bf16 (padded)
__device__ __nv_bfloat16 g_wl[(size_t)VP_ * H_];         // fc_w lo bf16 (padded)

// ---------------- helpers ----------------
static __device__ __forceinline__ unsigned long long pk2(float x, float y) {
    unsigned long long r;
    asm("mov.b64 %0, {%1, %2};" : "=l"(r) : "f"(x), "f"(y));
    return r;
}
static __device__ __forceinline__ float2 upk2(unsigned long long v) {
    float2 r;
    asm("mov.b64 {%0, %1}, %2;" : "=f"(r.x), "=f"(r.y) : "l"(v));
    return r;
}
static __device__ __forceinline__ unsigned long long ffma2(
    unsigned long long a, unsigned long long b, unsigned long long c) {
    unsigned long long d;
    asm("fma.rn.f32x2 %0, %1, %2, %3;" : "=l"(d) : "l"(a), "l"(b), "l"(c));
    return d;
}
static __device__ __forceinline__ uint32_t smem_u32(const void* p) {
    uint32_t a;
    asm("{ .reg .u64 t; cvta.to.shared.u64 t, %1; cvt.u32.u64 %0, t; }" : "=r"(a) : "l"(p));
    return a;
}

static __device__ __forceinline__ void ldsm4(uint32_t* r, uint32_t addr) {
    asm volatile("ldmatrix.sync.aligned.m8n8.x4.shared.b16 {%0,%1,%2,%3}, [%4];"
        : "=r"(r[0]), "=r"(r[1]), "=r"(r[2]), "=r"(r[3]) : "r"(addr));
}
static __device__ __forceinline__ void mma16816(
    float* c, const uint32_t* a, uint32_t b0, uint32_t b1)
{
    asm volatile(
        "mma.sync.aligned.m16n8k16.row.col.f32.bf16.bf16.f32 "
        "{%0,%1,%2,%3}, {%4,%5,%6,%7}, {%8,%9}, {%0,%1,%2,%3};"
        : "+f"(c[0]), "+f"(c[1]), "+f"(c[2]), "+f"(c[3])
        : "r"(a[0]), "r"(a[1]), "r"(a[2]), "r"(a[3]), "r"(b0), "r"(b1));
}
static __device__ __forceinline__ void cpasync16(uint32_t dst, const void* src) {
    asm volatile("cp.async.cg.shared.global [%0], [%1], 16;" :: "r"(dst), "l"(src));
}

// swizzled byte offset inside a 128-row x 64-bf16 (128B/row) smem tile
static __device__ __forceinline__ uint32_t tile_off(int row, int kb) {
    return (uint32_t)(row * 128 + ((kb ^ (row & 7)) << 4));
}

extern __shared__ char dynsm[];

// =====================================================================
// proj GEMM: out[r][g] = dot(A(r,:), Wih[g,:]) + bih + bhh
// =====================================================================
#define PROJ_SMEM (64 * 132 * 4 + 128 * 65 * 4)

__global__ __launch_bounds__(256) void proj_kernel(
    const float* __restrict__ Asrc, const int* __restrict__ xidx,
    const float* __restrict__ Wih, const float* __restrict__ bih,
    const float* __restrict__ bhh, float* __restrict__ out)
{
    float* smf = reinterpret_cast<float*>(dynsm);
    float (*As)[132] = reinterpret_cast<float(*)[132]>(smf);
    float (*Ws)[65]  = reinterpret_cast<float(*)[65]>(smf + 64 * 132);

    const int m0 = blockIdx.y * 64;
    const int n0 = blockIdx.x * 64;
    const int tid = threadIdx.x;

    for (int i = tid; i < 64 * 32; i += 256) {
        int r = i >> 5, c4 = (i & 31) * 4;
        const float* arow;
        if (xidx) {
            int gr = m0 + r;
            int b = gr & 15, t = gr >> 4;
            arow = Asrc + (size_t)xidx[b * T_ + t] * E_;
        } else {
            arow = Asrc + (size_t)(m0 + r) * H_;
        }
        float4 v = *reinterpret_cast<const float4*>(arow + c4);
        *reinterpret_cast<float4*>(&As[r][c4]) = v;
    }
    for (int i = tid; i < 64 * 32; i += 256) {
        int n = i >> 5, c4 = (i & 31) * 4;
        float4 v = *reinterpret_cast<const float4*>(Wih + (size_t)(n0 + n) * 128 + c4);
        Ws[c4 + 0][n] = v.x; Ws[c4 + 1][n] = v.y;
        Ws[c4 + 2][n] = v.z; Ws[c4 + 3][n] = v.w;
    }
    __syncthreads();

    const int tx = tid & 15, ty = tid >> 4;
    float acc[4][4] = {};
    #pragma unroll 8
    for (int k = 0; k < 128; k++) {
        float a[4], w[4];
        #pragma unroll
        for (int i = 0; i < 4; i++) a[i] = As[ty * 4 + i][k];
        #pragma unroll
        for (int j = 0; j < 4; j++) w[j] = Ws[k][tx * 4 + j];
        #pragma unroll
        for (int i = 0; i < 4; i++)
            #pragma unroll
            for (int j = 0; j < 4; j++)
                acc[i][j] = fmaf(a[i], w[j], acc[i][j]);
    }

    #pragma unroll
    for (int j = 0; j < 4; j++) {
        int n = n0 + tx * 4 + j;
        float bv = bih[n] + bhh[n];
        #pragma unroll
        for (int i = 0; i < 4; i++)
            out[(size_t)(m0 + ty * 4 + i) * G_ + n] = acc[i][j] + bv;
    }
}

// =====================================================================
// LSTM recurrence — cluster of 4 CTAs per batch element, weights in regs.
// grid = 64 CTAs (16 batch x 4 gate-types), 128 threads each.
// =====================================================================
__global__ __launch_bounds__(128, 1) __cluster_dims__(4, 1, 1)
void lstm_cluster(const float* __restrict__ xproj, const float* __restrict__ Whh,
                  float* __restrict__ y, __nv_bfloat16* __restrict__ yh,
                  __nv_bfloat16* __restrict__ yl, int layer,
                  float* __restrict__ h_out, float* __restrict__ c_out)
{
    __shared__ __align__(16) float hs[H_];
    __shared__ __align__(16) float gs[2][G_];
    const int tid = threadIdx.x;
    const int b = blockIdx.x >> 2;
    uint32_t rank;
    asm("mov.u32 %0, %%cluster_ctarank;" : "=r"(rank));
    const int row = (int)rank * H_ + tid;

    // gate row weights -> registers, packed f32x2
    unsigned long long wp[64];
    {
        const float4* w4 = reinterpret_cast<const float4*>(Whh + (size_t)row * H_);
        #pragma unroll
        for (int k = 0; k < 32; k++) {
            float4 v = w4[k];
            wp[2 * k]     = pk2(v.x, v.y);
            wp[2 * k + 1] = pk2(v.z, v.w);
        }
    }

    // peer addresses of gs[p][row] in each cluster CTA
    uint32_t pa0[4], pa1[4];
    {
        uint32_t l0 = smem_u32(&gs[0][row]);
        uint32_t l1 = smem_u32(&gs[1][row]);
        #pragma unroll
        for (int r = 0; r < 4; r++) {
            asm("mapa.shared::cluster.u32 %0, %1, %2;" : "=r"(pa0[r]) : "r"(l0), "r"(r));
            asm("mapa.shared::cluster.u32 %0, %1, %2;" : "=r"(pa1[r]) : "r"(l1), "r"(r));
        }
    }

    float c = 0.f;
    hs[tid] = 0.f;
    __syncthreads();

    int p = 0;
    for (int t = 0; t < T_; t++) {
        float xv = xproj[((size_t)t * B_ + b) * G_ + row];

        unsigned long long a0 = 0ull, a1 = 0ull;
        const ulonglong2* h2 = reinterpret_cast<const ulonglong2*>(hs);
        #pragma unroll
        for (int k = 0; k < 32; k++) {
            ulonglong2 hv = h2[k];
            a0 = ffma2(wp[2 * k],     hv.x, a0);
            a1 = ffma2(wp[2 * k + 1], hv.y, a1);
        }
        float2 s0 = upk2(a0), s1 = upk2(a1);
        float gval = (s0.x + s0.y) + (s1.x + s1.y) + xv;

        // broadcast my gate value into gs[p][row] of all 4 cluster CTAs
        #pragma unroll
        for (int r = 0; r < 4; r++) {
            uint32_t dst = p ? pa1[r] : pa0[r];
            asm volatile("st.shared::cluster.f32 [%0], %1;" :: "r"(dst), "f"(gval) : "memory");
        }
        asm volatile("barrier.cluster.arrive.aligned;" ::: "memory");
        asm volatile("barrier.cluster.wait.aligned;" ::: "memory");

        // redundant elementwise update (all CTAs, deterministic)
        float gi = gs[p][tid];
        float gf = gs[p][H_ + tid];
        float gg = gs[p][2 * H_ + tid];
        float go = gs[p][3 * H_ + tid];
        float iv = __fdividef(1.f, 1.f + __expf(-gi));
        float fv = __fdividef(1.f, 1.f + __expf(-gf));
        float e2 = __expf(2.f * gg);
        float gt = 1.f - __fdividef(2.f, e2 + 1.f);
        float ov = __fdividef(1.f, 1.f + __expf(-go));
        c = fv * c + iv * gt;
        float ec = __expf(2.f * c);
        float th = 1.f - __fdividef(2.f, ec + 1.f);
        float h = ov * th;
        hs[tid] = h;

        if (rank == 0) {
            if (layer == 0) {
                y[((size_t)t * B_ + b) * H_ + tid] = h;
            } else {
                __nv_bfloat16 hh = __float2bfloat16(h);
                size_t r = ((size_t)b * T_ + t) * H_ + tid;
                yh[r] = hh;
                yl[r] = __float2bfloat16(h - __bfloat162float(hh));
            }
        }
        __syncthreads();
        p ^= 1;
    }

    if (rank == 0) {
        h_out[b * H_ + tid] = hs[tid];
        c_out[b * H_ + tid] = c;
    }
}

// =====================================================================
// W conversion: fc_w fp32 [V,H] -> bf16 hi/lo, padded to VP_ rows.
// =====================================================================
__global__ __launch_bounds__(256) void wconv_kernel(
    const float* __restrict__ W, __nv_bfloat16* __restrict__ Wh,
    __nv_bfloat16* __restrict__ Wl)
{
    size_t idx = (size_t)blockIdx.x * 256 + threadIdx.x;   // one float4 each
    if (idx >= (size_t)VP_ * H_ / 4) return;
    float4 v = (idx < (size_t)V_ * H_ / 4)
        ? reinterpret_cast<const float4*>(W)[idx]
        : make_float4(0.f, 0.f, 0.f, 0.f);
    __nv_bfloat16 h0 = __float2bfloat16(v.x), h1 = __float2bfloat16(v.y);
    __nv_bfloat16 h2 = __float2bfloat16(v.z), h3 = __float2bfloat16(v.w);
    __nv_bfloat162 ph0; ph0.x = h0; ph0.y = h1;
    __nv_bfloat162 ph1; ph1.x = h2; ph1.y = h3;
    __nv_bfloat162 pl0, pl1;
    pl0.x = __float2bfloat16(v.x - __bfloat162float(h0));
    pl0.y = __float2bfloat16(v.y - __bfloat162float(h1));
    pl1.x = __float2bfloat16(v.z - __bfloat162float(h2));
    pl1.y = __float2bfloat16(v.w - __bfloat162float(h3));
    reinterpret_cast<__nv_bfloat162*>(Wh)[2 * idx]     = ph0;
    reinterpret_cast<__nv_bfloat162*>(Wh)[2 * idx + 1] = ph1;
    reinterpret_cast<__nv_bfloat162*>(Wl)[2 * idx]     = pl0;
    reinterpret_cast<__nv_bfloat162*>(Wl)[2 * idx + 1] = pl1;
}

// =====================================================================
// FC: logits = y1 @ fc_w^T + fc_b via mma.sync bf16 3-product split
// (virtual K = 384 = [Ah·Wh | Al·Wh | Ah·Wl]).
// CTA tile 128x128, 8 warps (warp tile 32x64), cp.async double-buffered
// 64-wide K chunks, ldmatrix fragment feeds, direct float2 epilogue.
// smem: buf0 A 16K | buf0 W 16K | buf1 A 16K | buf1 W 16K | bias 512B
// =====================================================================
#define FCT_SMEM (65536 + 512)

static __device__ __forceinline__ void fc_stage(
    uint32_t sb, int buf, const __nv_bfloat16* __restrict__ A,
    const __nv_bfloat16* __restrict__ W, int m0, int n0, int kk, int tid)
{
    uint32_t ab = sb + (uint32_t)buf * 32768;
    uint32_t wb = ab + 16384;
    #pragma unroll
    for (int ii = 0; ii < 4; ii++) {
        int i = tid + ii * 256;
        int row = i >> 3, kb = i & 7;
        uint32_t so = tile_off(row, kb);
        cpasync16(ab + so, A + (size_t)(m0 + row) * H_ + kk + kb * 8);
        cpasync16(wb + so, W + (size_t)(n0 + row) * H_ + kk + kb * 8);
    }
    asm volatile("cp.async.commit_group;" ::: "memory");
}

__global__ __launch_bounds__(256, 2) void fc_mma_kernel(
    const __nv_bfloat16* __restrict__ Ah, const __nv_bfloat16* __restrict__ Al,
    const __nv_bfloat16* __restrict__ Wh, const __nv_bfloat16* __restrict__ Wl,
    const float* __restrict__ bias, float* __restrict__ out)
{
    char* smb = dynsm;
    const uint32_t sb = smem_u32(smb);
    const int tid = threadIdx.x;
    const int lane = tid & 31, wid = tid >> 5;
    const int n0 = blockIdx.x * 128;
    const int m0 = blockIdx.y * 128;
    const int m_off = (wid >> 1) * 32;   // warp m offset (0..96)
    const int n_off = (wid & 1) * 64;    // warp n offset (0/64)
    float* sbias = reinterpret_cast<float*>(smb + 65536);

    if (tid < 128) sbias[tid] = (n0 + tid < V_) ? bias[n0 + tid] : 0.f;

    float acc[2][8][4];
    #pragma unroll
    for (int mt = 0; mt < 2; mt++)
        #pragma unroll
        for (int nt = 0; nt < 8; nt++)
            #pragma unroll
            for (int q = 0; q < 4; q++) acc[mt][nt][q] = 0.f;

    // virtual-K chunk sources: (Ah,Wh) (Ah,Wh) (Al,Wh) (Al,Wh) (Ah,Wl) (Ah,Wl)
    fc_stage(sb, 0, Ah, Wh, m0, n0, 0, tid);

    #pragma unroll
    for (int c = 0; c < 6; c++) {
        if (c < 5) {
            int cn = c + 1;
            const __nv_bfloat16* An = (cn < 2 || cn >= 4) ? Ah : Al;
            const __nv_bfloat16* Wn = (cn < 4) ? Wh : Wl;
            fc_stage(sb, cn & 1, An, Wn, m0, n0, (cn & 1) * 64, tid);
            asm volatile("cp.async.wait_group 1;" ::: "memory");
        } else {
            asm volatile("cp.async.wait_group 0;" ::: "memory");
        }
        __syncthreads();

        uint32_t ab = sb + (uint32_t)(c & 1) * 32768;
        uint32_t wb = ab + 16384;
        #pragma unroll
        for (int s = 0; s < 4; s++) {
            uint32_t afr[2][4];
            #pragma unroll
            for (int mt = 0; mt < 2; mt++) {
                int row = m_off + mt * 16 + (lane & 15);
                int kb = s * 2 + (lane >> 4);
                ldsm4(afr[mt], ab + tile_off(row, kb));
            }
            uint32_t bfr[4][4];
            #pragma unroll
            for (int nq = 0; nq < 4; nq++) {
                int row = n_off + nq * 16 + (lane & 7) + ((lane >> 3) & 1) * 8;
                int kb = s * 2 + (lane >> 4);
                ldsm4(bfr[nq], wb + tile_off(row, kb));
            }
            #pragma unroll
            for (int mt = 0; mt < 2; mt++)
                #pragma unroll
                for (int nq = 0; nq < 4; nq++) {
                    mma16816(acc[mt][nq * 2],     afr[mt], bfr[nq][0], bfr[nq][2]);
                    mma16816(acc[mt][nq * 2 + 1], afr[mt], bfr[nq][1], bfr[nq][3]);
                }
        }
        __syncthreads();
    }

    // epilogue: c0,c1 -> (row, col..col+1); c2,c3 -> (row+8, same cols)
    #pragma unroll
    for (int mt = 0; mt < 2; mt++) {
        int r0 = m0 + m_off + mt * 16 + (lane >> 2);
        #pragma unroll
        for (int nt = 0; nt < 8; nt++) {
            int nl = n_off + nt * 8 + (lane & 3) * 2;
            int cN = n0 + nl;
            if (cN < V_) {
                float b0 = sbias[nl], b1 = sbias[nl + 1];
                float2 o;
                o.x = acc[mt][nt][0] + b0; o.y = acc[mt][nt][1] + b1;
                *reinterpret_cast<float2*>(out + (size_t)r0 * V_ + cN) = o;
                o.x = acc[mt][nt][2] + b0; o.y = acc[mt][nt][3] + b1;
                *reinterpret_cast<float2*>(out + (size_t)(r0 + 8) * V_ + cN) = o;
            }
        }
    }
}

// =====================================================================
// launch
// =====================================================================
extern "C" void kernel_launch(void* const* d_in, const int* in_sizes, int n_in,
                              void* d_out, int out_size)
{
    const int*   x    = (const int*)  d_in[0];
    const float* emb  = (const float*)d_in[1];
    const float* Wih0 = (const float*)d_in[2];
    const float* Whh0 = (const float*)d_in[3];
    const float* bih0 = (const float*)d_in[4];
    const float* bhh0 = (const float*)d_in[5];
    const float* Wih1 = (const float*)d_in[6];
    const float* Whh1 = (const float*)d_in[7];
    const float* bih1 = (const float*)d_in[8];
    const float* bhh1 = (const float*)d_in[9];
    const float* fcw  = (const float*)d_in[10];
    const float* fcb  = (const float*)d_in[11];
    float* out = (float*)d_out;

    float *xproj, *y0;
    __nv_bfloat16 *ah, *al, *wh, *wl;
    cudaGetSymbolAddress((void**)&xproj, g_xproj);
    cudaGetSymbolAddress((void**)&y0, g_y0);
    cudaGetSymbolAddress((void**)&ah, g_ah);
    cudaGetSymbolAddress((void**)&al, g_al);
    cudaGetSymbolAddress((void**)&wh, g_wh);
    cudaGetSymbolAddress((void**)&wl, g_wl);

    cudaFuncSetAttribute(proj_kernel, cudaFuncAttributeMaxDynamicSharedMemorySize, PROJ_SMEM);
    cudaFuncSetAttribute(fc_mma_kernel, cudaFuncAttributeMaxDynamicSharedMemorySize, FCT_SMEM);

    // output layout: logits [B,T,V] || h [L,B,H] || c [L,B,H]
    const size_t NL = (size_t)B_ * T_ * V_;
    float* h_base = out + NL;
    float* c_base = out + NL + 2 * B_ * H_;

    // W conversion (independent of LSTM chain; overlaps in-order stream fine)
    wconv_kernel<<<(VP_ * H_ / 4 + 255) / 256, 256>>>(fcw, wh, wl);
    // layer 0
    proj_kernel<<<dim3(8, 64), 256, PROJ_SMEM>>>(emb, x, Wih0, bih0, bhh0, xproj);
    lstm_cluster<<<64, 128>>>(xproj, Whh0, y0, ah, al, 0, h_base, c_base);
    // layer 1
    proj_kernel<<<dim3(8, 64), 256, PROJ_SMEM>>>(y0, nullptr, Wih1, bih1, bhh1, xproj);
    lstm_cluster<<<64, 128>>>(xproj, Whh1, y0, ah, al, 1, h_base + B_ * H_, c_base + B_ * H_);
    // output projection (HMMA bf16 3-product split, virtual K=384)
    fc_mma_kernel<<<dim3((V_ + 127) / 128, 32), 256, FCT_SMEM>>>(ah, al, wh, wl, fcb, out);
}